// round 2
// baseline (speedup 1.0000x reference)
#include <cuda_runtime.h>
#include <cstdint>

// Problem constants (BertTagger CRF): B=512, T=512, K=128
#define BB 512
#define TT 512
#define KK 128
#define START_TAG 126
#define STOP_TAG 127

__device__ float g_absdiff[BB];
__device__ int   g_order[BB];

typedef unsigned long long ull;

__device__ __forceinline__ ull ffma2(ull a, ull b, ull c) {
    ull d;
    asm("fma.rn.f32x2 %0, %1, %2, %3;" : "=l"(d) : "l"(a), "l"(b), "l"(c));
    return d;
}
__device__ __forceinline__ ull addf2(ull a, ull b) {
    ull d;
    asm("add.rn.f32x2 %0, %1, %2;" : "=l"(d) : "l"(a), "l"(b));
    return d;
}
__device__ __forceinline__ ull packf2(float x, float y) {
    ull d;
    asm("mov.b64 %0, {%1, %2};" : "=l"(d) : "f"(x), "f"(y));
    return d;
}
__device__ __forceinline__ void unpackf2(ull v, float& x, float& y) {
    asm("mov.b64 {%0, %1}, %2;" : "=f"(x), "=f"(y) : "l"(v));
}

// -------- rank-by-length scheduling: longest sequences get lowest blockIdx ----
__global__ void order_kernel(const int* __restrict__ lengths) {
    __shared__ int sl[BB];
    int b = threadIdx.x;
    sl[b] = lengths[b];
    __syncthreads();
    int lb = sl[b];
    int r = 0;
    #pragma unroll 8
    for (int i = 0; i < BB; i++) {
        int li = sl[i];
        r += (li > lb) || (li == lb && i < b);
    }
    g_order[r] = b;
}

// -------- block reductions (128 threads, 4 warps) --------
__device__ __forceinline__ float block_max(float v, float* red) {
    #pragma unroll
    for (int o = 16; o > 0; o >>= 1)
        v = fmaxf(v, __shfl_xor_sync(0xffffffffu, v, o));
    if ((threadIdx.x & 31) == 0) red[threadIdx.x >> 5] = v;
    __syncthreads();
    float r = fmaxf(fmaxf(red[0], red[1]), fmaxf(red[2], red[3]));
    __syncthreads();
    return r;
}
__device__ __forceinline__ float block_sum(float v, float* red) {
    #pragma unroll
    for (int o = 16; o > 0; o >>= 1)
        v += __shfl_xor_sync(0xffffffffu, v, o);
    if ((threadIdx.x & 31) == 0) red[threadIdx.x >> 5] = v;
    __syncthreads();
    float r = red[0] + red[1] + red[2] + red[3];
    __syncthreads();
    return r;
}

// -------- main CRF kernel: one CTA per batch element --------
__global__ __launch_bounds__(128) void crf_kernel(
    const float* __restrict__ feats,
    const float* __restrict__ trans,
    const int*   __restrict__ tags,
    const int*   __restrict__ lengths)
{
    __shared__ __align__(16) float expA[KK];
    __shared__ float red[4];

    const int j = threadIdx.x;
    const int b = g_order[blockIdx.x];
    const int len = lengths[b];

    // E row j = exp(trans[j, :]) packed into 64 f32x2 registers
    ull E2[64];
    {
        const float2* tr2 = (const float2*)(trans + j * KK);
        #pragma unroll
        for (int i = 0; i < 64; i++) {
            float2 tv = tr2[i];
            E2[i] = packf2(__expf(tv.x), __expf(tv.y));
        }
    }

    // init: alpha0 = NEG everywhere, 0 at START; m = 0
    float val = (j == START_TAG) ? 0.0f : -10000.0f;
    float m = 0.0f;
    expA[j] = (j == START_TAG) ? 1.0f : 0.0f;
    __syncthreads();

    const float* frow = feats + (size_t)b * TT * KK;
    const unsigned sbase = (unsigned)__cvta_generic_to_shared(expA);

    float emit = frow[j];  // t=0 emit (len >= 1 always)

    for (int t = 0; t < len; t++) {
        // prefetch next step's emission
        float emit_next = 0.0f;
        if (t + 1 < len) emit_next = frow[(t + 1) * KK + j];

        // dot: sum_k E[j,k] * expA[k]  (packed f32x2, 4 accumulator chains)
        // NOTE: loads MUST be volatile — expA changes every iteration; a
        // non-volatile pure asm would legally be hoisted/CSE'd out of the loop.
        ull a0 = 0ull, a1 = 0ull, a2 = 0ull, a3 = 0ull;
        #pragma unroll
        for (int i = 0; i < 64; i += 8) {
            ull x0, x1, x2, x3, x4, x5, x6, x7;
            asm volatile("ld.shared.v2.b64 {%0,%1},[%2];" : "=l"(x0), "=l"(x1) : "r"(sbase + i * 8));
            asm volatile("ld.shared.v2.b64 {%0,%1},[%2];" : "=l"(x2), "=l"(x3) : "r"(sbase + i * 8 + 16));
            asm volatile("ld.shared.v2.b64 {%0,%1},[%2];" : "=l"(x4), "=l"(x5) : "r"(sbase + i * 8 + 32));
            asm volatile("ld.shared.v2.b64 {%0,%1},[%2];" : "=l"(x6), "=l"(x7) : "r"(sbase + i * 8 + 48));
            a0 = ffma2(E2[i + 0], x0, a0);
            a1 = ffma2(E2[i + 1], x1, a1);
            a2 = ffma2(E2[i + 2], x2, a2);
            a3 = ffma2(E2[i + 3], x3, a3);
            a0 = ffma2(E2[i + 4], x4, a0);
            a1 = ffma2(E2[i + 5], x5, a1);
            a2 = ffma2(E2[i + 6], x6, a2);
            a3 = ffma2(E2[i + 7], x7, a3);
        }
        ull s = addf2(addf2(a0, a1), addf2(a2, a3));
        float lo, hi;
        unpackf2(s, lo, hi);
        float dot = lo + hi;

        // new alpha[j] (absolute). dot==0 only when E row is all-zero (START row);
        // the floor keeps it finite and numerically negligible downstream.
        val = emit + m + __logf(fmaxf(dot, 1e-30f));
        emit = emit_next;

        // block max of new alpha -> m ; renormalize expA
        float mv = val;
        #pragma unroll
        for (int o = 16; o > 0; o >>= 1)
            mv = fmaxf(mv, __shfl_xor_sync(0xffffffffu, mv, o));
        if ((j & 31) == 0) red[j >> 5] = mv;
        __syncthreads();  // also guarantees all dot-reads of expA are done
        m = fmaxf(fmaxf(red[0], red[1]), fmaxf(red[2], red[3]));
        expA[j] = __expf(val - m);
        __syncthreads();
    }

    // terminal: logsumexp_j( alpha[j] + trans[STOP, j] )
    float term = val + trans[STOP_TAG * KK + j];
    float tm = block_max(term, red);
    float ssum = block_sum(__expf(term - tm), red);
    float fwd = tm + __logf(ssum);

    // gold score
    const int* trow = tags + b * TT;
    float g = 0.0f;
    for (int t = j; t < TT; t += 128) {
        if (t < len) {
            int tag  = trow[t];
            int prev = (t == 0) ? START_TAG : trow[t - 1];
            g += trans[tag * KK + prev] + frow[t * KK + tag];
        }
    }
    if (j == 0) g += trans[STOP_TAG * KK + trow[len - 1]];
    float gold = block_sum(g, red);

    if (j == 0) g_absdiff[b] = fabsf(fwd - gold);
}

// -------- deterministic final reduction --------
__global__ void reduce_kernel(float* __restrict__ out, int out_size) {
    __shared__ float s[BB];
    int t = threadIdx.x;
    s[t] = g_absdiff[t];
    __syncthreads();
    #pragma unroll
    for (int off = 256; off > 0; off >>= 1) {
        if (t < off) s[t] += s[t + off];
        __syncthreads();
    }
    float r = s[0] * (1.0f / (float)BB);
    for (int i = t; i < out_size; i += BB) out[i] = r;
}

extern "C" void kernel_launch(void* const* d_in, const int* in_sizes, int n_in,
                              void* d_out, int out_size) {
    // Identify inputs by element count (all four are distinct) — immune to ordering.
    const float* feats   = nullptr;
    const float* trans   = nullptr;
    const int*   tags    = nullptr;
    const int*   lengths = nullptr;
    for (int i = 0; i < n_in; i++) {
        switch (in_sizes[i]) {
            case BB * TT * KK: feats   = (const float*)d_in[i]; break;  // 33554432
            case KK * KK:      trans   = (const float*)d_in[i]; break;  // 16384
            case BB * TT:      tags    = (const int*)d_in[i];   break;  // 262144
            case BB:           lengths = (const int*)d_in[i];   break;  // 512
            default: break;
        }
    }

    order_kernel<<<1, BB>>>(lengths);
    crf_kernel<<<BB, 128>>>(feats, trans, tags, lengths);
    reduce_kernel<<<1, BB>>>((float*)d_out, out_size);
}

// round 3
// speedup vs baseline: 1.1727x; 1.1727x over previous
#include <cuda_runtime.h>
#include <cstdint>

// Problem constants (BertTagger CRF): B=512, T=512, K=128
#define BB 512
#define TT 512
#define KK 128
#define START_TAG 126
#define STOP_TAG 127

__device__ float g_absdiff[BB];
__device__ int   g_order[BB];
__device__ float g_c;       // static per-step scale: log(max_j sum_k exp(trans[j,k])) + slack

typedef unsigned long long ull;

__device__ __forceinline__ ull ffma2(ull a, ull b, ull c) {
    ull d;
    asm("fma.rn.f32x2 %0, %1, %2, %3;" : "=l"(d) : "l"(a), "l"(b), "l"(c));
    return d;
}
__device__ __forceinline__ ull addf2(ull a, ull b) {
    ull d;
    asm("add.rn.f32x2 %0, %1, %2;" : "=l"(d) : "l"(a), "l"(b));
    return d;
}
__device__ __forceinline__ ull packf2(float x, float y) {
    ull d;
    asm("mov.b64 %0, {%1, %2};" : "=l"(d) : "f"(x), "f"(y));
    return d;
}
__device__ __forceinline__ void unpackf2(ull v, float& x, float& y) {
    asm("mov.b64 {%0, %1}, %2;" : "=f"(x), "=f"(y) : "l"(v));
}

// -------- counting-sort ordering: longest sequences get lowest blockIdx ------
__global__ void order_kernel(const int* __restrict__ lengths) {
    __shared__ int hist[TT];   // bin = len-1 in [0, 511]
    __shared__ int sfx[TT];    // inclusive suffix sums of hist
    __shared__ int cur[TT];    // tie cursors
    int b = threadIdx.x;
    hist[b] = 0; cur[b] = 0;
    __syncthreads();
    int len = lengths[b];
    int bin = len - 1;
    atomicAdd(&hist[bin], 1);
    __syncthreads();
    sfx[b] = hist[b];
    __syncthreads();
    // Kogge-Stone inclusive suffix scan: sfx[i] = sum_{k>=i} hist[k]
    #pragma unroll
    for (int d = 1; d < TT; d <<= 1) {
        int v = (b + d < TT) ? sfx[b + d] : 0;
        __syncthreads();
        sfx[b] += v;
        __syncthreads();
    }
    int base = (bin < TT - 1) ? sfx[bin + 1] : 0;  // # strictly longer
    int pos = base + atomicAdd(&cur[bin], 1);
    g_order[pos] = b;
}

// -------- static scale: c = log(max_j sum_k exp(trans[j,k])) + 2.5 ----------
__global__ void shat_kernel(const float* __restrict__ trans) {
    __shared__ float red[4];
    int j = threadIdx.x;  // 128 threads
    float s = 0.0f;
    #pragma unroll 8
    for (int k = 0; k < KK; k++) s += __expf(trans[j * KK + k]);
    #pragma unroll
    for (int o = 16; o > 0; o >>= 1)
        s = fmaxf(s, __shfl_xor_sync(0xffffffffu, s, o));
    if ((j & 31) == 0) red[j >> 5] = s;
    __syncthreads();
    if (j == 0) {
        float mx = fmaxf(fmaxf(red[0], red[1]), fmaxf(red[2], red[3]));
        g_c = __logf(mx) + 2.5f;
    }
}

// -------- block reductions (128 threads, 4 warps) --------
__device__ __forceinline__ float block_max(float v, float* red) {
    #pragma unroll
    for (int o = 16; o > 0; o >>= 1)
        v = fmaxf(v, __shfl_xor_sync(0xffffffffu, v, o));
    if ((threadIdx.x & 31) == 0) red[threadIdx.x >> 5] = v;
    __syncthreads();
    float r = fmaxf(fmaxf(red[0], red[1]), fmaxf(red[2], red[3]));
    __syncthreads();
    return r;
}
__device__ __forceinline__ float block_sum(float v, float* red) {
    #pragma unroll
    for (int o = 16; o > 0; o >>= 1)
        v += __shfl_xor_sync(0xffffffffu, v, o);
    if ((threadIdx.x & 31) == 0) red[threadIdx.x >> 5] = v;
    __syncthreads();
    float r = red[0] + red[1] + red[2] + red[3];
    __syncthreads();
    return r;
}

// -------- main CRF kernel: one CTA per batch element --------
__global__ __launch_bounds__(128, 3) void crf_kernel(
    const float* __restrict__ feats,
    const float* __restrict__ trans,
    const int*   __restrict__ tags,
    const int*   __restrict__ lengths)
{
    __shared__ __align__(16) float buf[2][KK];  // double-buffered P = exp(alpha - M)
    __shared__ float wmax[4];
    __shared__ float red[4];

    const int j = threadIdx.x;
    const int b = g_order[blockIdx.x];
    const int len = lengths[b];
    const float c = g_c;

    // E row j = exp(trans[j, :]) packed into 64 f32x2 registers
    ull E2[64];
    {
        const float2* tr2 = (const float2*)(trans + j * KK);
        #pragma unroll
        for (int i = 0; i < 64; i++) {
            float2 tv = tr2[i];
            E2[i] = packf2(__expf(tv.x), __expf(tv.y));
        }
    }

    // init: P0 one-hot at START, M = 0
    float P = (j == START_TAG) ? 1.0f : 0.0f;
    float M = 0.0f;
    buf[0][j] = P;
    __syncthreads();

    const float* frow = feats + (size_t)b * TT * KK;
    const unsigned sbase = (unsigned)__cvta_generic_to_shared(&buf[0][0]);

    // emit prefetch pipeline, distance 2 (LDG latency > step time)
    float emit0 = frow[j];
    float emit1 = (len > 1) ? frow[KK + j] : 0.0f;

    float corr = 1.0f;   // dot multiplier from lazy renorm (applied one step late)
    float lcorr = 0.0f;  // matching log-scale addition to M

    for (int t = 0; t < len; t++) {
        float e2 = 0.0f;
        if (t + 2 < len) e2 = frow[(t + 2) * KK + j];

        // dot_j = sum_k E[j,k] * P_prev[k]   (packed f32x2, 4 chains)
        const unsigned sb = sbase + ((unsigned)(t & 1) << 9);
        ull a0 = 0ull, a1 = 0ull, a2 = 0ull, a3 = 0ull;
        #pragma unroll
        for (int i = 0; i < 64; i += 8) {
            ull x0, x1, x2, x3, x4, x5, x6, x7;
            asm volatile("ld.shared.v2.b64 {%0,%1},[%2];" : "=l"(x0), "=l"(x1) : "r"(sb + i * 8));
            asm volatile("ld.shared.v2.b64 {%0,%1},[%2];" : "=l"(x2), "=l"(x3) : "r"(sb + i * 8 + 16));
            asm volatile("ld.shared.v2.b64 {%0,%1},[%2];" : "=l"(x4), "=l"(x5) : "r"(sb + i * 8 + 32));
            asm volatile("ld.shared.v2.b64 {%0,%1},[%2];" : "=l"(x6), "=l"(x7) : "r"(sb + i * 8 + 48));
            a0 = ffma2(E2[i + 0], x0, a0);
            a1 = ffma2(E2[i + 1], x1, a1);
            a2 = ffma2(E2[i + 2], x2, a2);
            a3 = ffma2(E2[i + 3], x3, a3);
            a0 = ffma2(E2[i + 4], x4, a0);
            a1 = ffma2(E2[i + 5], x5, a1);
            a2 = ffma2(E2[i + 6], x6, a2);
            a3 = ffma2(E2[i + 7], x7, a3);
        }
        ull s = addf2(addf2(a0, a1), addf2(a2, a3));
        float lo, hi;
        unpackf2(s, lo, hi);
        float dot = (lo + hi) * corr;

        // P_new = exp(emit - c) * dot ;  alpha = log P + M
        P = __expf(emit0 - c) * dot;
        M += c + lcorr;
        corr = 1.0f; lcorr = 0.0f;
        emit0 = emit1; emit1 = e2;

        if (t != len - 1) {
            // lazy renorm: publish warp maxes through this step's barrier;
            // applied to next step's dot (off the critical path).
            bool rn = ((t & 3) == 3);
            if (rn) {
                float mv = P;
                #pragma unroll
                for (int o = 16; o > 0; o >>= 1)
                    mv = fmaxf(mv, __shfl_xor_sync(0xffffffffu, mv, o));
                if ((j & 31) == 0) wmax[j >> 5] = mv;
            }
            buf[(t + 1) & 1][j] = P;
            __syncthreads();
            if (rn) {
                float mx = fmaxf(fmaxf(wmax[0], wmax[1]), fmaxf(wmax[2], wmax[3]));
                corr = __frcp_rn(mx);
                lcorr = __logf(mx);
            }
        }
    }

    // terminal: logsumexp_j( alpha[j] + trans[STOP, j] ),  alpha = log P + M
    float term = __logf(fmaxf(P, 1e-37f)) + M + trans[STOP_TAG * KK + j];
    float tm = block_max(term, red);
    float ssum = block_sum(__expf(term - tm), red);
    float fwd = tm + __logf(ssum);

    // gold score
    const int* trow = tags + b * TT;
    float g = 0.0f;
    for (int t = j; t < TT; t += 128) {
        if (t < len) {
            int tag  = trow[t];
            int prev = (t == 0) ? START_TAG : trow[t - 1];
            g += trans[tag * KK + prev] + frow[t * KK + tag];
        }
    }
    if (j == 0) g += trans[STOP_TAG * KK + trow[len - 1]];
    float gold = block_sum(g, red);

    if (j == 0) g_absdiff[b] = fabsf(fwd - gold);
}

// -------- deterministic final reduction --------
__global__ void reduce_kernel(float* __restrict__ out, int out_size) {
    __shared__ float s[BB];
    int t = threadIdx.x;
    s[t] = g_absdiff[t];
    __syncthreads();
    #pragma unroll
    for (int off = 256; off > 0; off >>= 1) {
        if (t < off) s[t] += s[t + off];
        __syncthreads();
    }
    float r = s[0] * (1.0f / (float)BB);
    for (int i = t; i < out_size; i += BB) out[i] = r;
}

extern "C" void kernel_launch(void* const* d_in, const int* in_sizes, int n_in,
                              void* d_out, int out_size) {
    // Identify inputs by element count (all four are distinct) — immune to ordering.
    const float* feats   = nullptr;
    const float* trans   = nullptr;
    const int*   tags    = nullptr;
    const int*   lengths = nullptr;
    for (int i = 0; i < n_in; i++) {
        switch (in_sizes[i]) {
            case BB * TT * KK: feats   = (const float*)d_in[i]; break;  // 33554432
            case KK * KK:      trans   = (const float*)d_in[i]; break;  // 16384
            case BB * TT:      tags    = (const int*)d_in[i];   break;  // 262144
            case BB:           lengths = (const int*)d_in[i];   break;  // 512
            default: break;
        }
    }

    order_kernel<<<1, BB>>>(lengths);
    shat_kernel<<<1, KK>>>(trans);
    crf_kernel<<<BB, 128>>>(feats, trans, tags, lengths);
    reduce_kernel<<<1, BB>>>((float*)d_out, out_size);
}